// round 15
// baseline (speedup 1.0000x reference)
#include <cuda_runtime.h>
#include <cuda_fp16.h>
#include <math.h>
#include <stdint.h>

#define NN 50000
#define EE 800000
#define H1 8
#define NEG_SLOPE 0.2f
#define SCAN_BC ((NN + 1023) / 1024)   // 49

// ---------------- scratch (device globals; no allocation allowed) ----------------
__device__ __half g_feat1h[NN * 256];        // layer1 features (fp16 gather)
__device__ float  g_el1[NN * H1];
__device__ float  g_er1[NN * H1];
__device__ float  g_f2[NN * 64];             // [ feat2 (0..31) | res2 (32..63) ] fp32
__device__ __half g_f2h[NN * 32];            // fp16 copy of feat2 (agg2 gather)
__device__ float  g_el2[NN];
__device__ float  g_er2[NN];
__device__ __half g_w1t[256 * 256];          // W1^T [n][k] fp16
__device__ __half g_wct[64 * 256];           // [W2|resW2]^T [n][k] fp16
__device__ int   g_deg[NN];                  // zero-init at load; self-reset each run
__device__ int   g_rowoff[NN + 1];
__device__ int   g_cursor[NN];
__device__ int   g_csr_src[EE];
__device__ int   g_bsum[SCAN_BC];
__device__ int   g_flag[SCAN_BC];

// ---------------- helpers ----------------
__device__ __forceinline__ uint32_t smem_u32(const void* p) {
    uint32_t a;
    asm("{ .reg .u64 t; cvta.to.shared.u64 t, %1; cvt.u32.u64 %0, t; }" : "=r"(a) : "l"(p));
    return a;
}
__device__ __forceinline__ void ldsm_x4(uint32_t (&r)[4], const void* p) {
    uint32_t a = smem_u32(p);
    asm volatile("ldmatrix.sync.aligned.m8n8.x4.shared.b16 {%0,%1,%2,%3}, [%4];"
                 : "=r"(r[0]), "=r"(r[1]), "=r"(r[2]), "=r"(r[3]) : "r"(a));
}
__device__ __forceinline__ void mma_f16(float (&d)[4], const uint32_t (&a)[4],
                                        uint32_t b0, uint32_t b1) {
    asm volatile("mma.sync.aligned.m16n8k16.row.col.f32.f16.f16.f32 "
                 "{%0,%1,%2,%3},{%4,%5,%6,%7},{%8,%9},{%0,%1,%2,%3};"
                 : "+f"(d[0]), "+f"(d[1]), "+f"(d[2]), "+f"(d[3])
                 : "r"(a[0]), "r"(a[1]), "r"(a[2]), "r"(a[3]), "r"(b0), "r"(b1));
}
__device__ __forceinline__ void cp16(uint32_t dst, const void* src) {
    asm volatile("cp.async.cg.shared.global [%0], [%1], 16;" :: "r"(dst), "l"(src));
}
#define CP_COMMIT() asm volatile("cp.async.commit_group;" ::: "memory")
#define CP_WAIT0()  asm volatile("cp.async.wait_group 0;" ::: "memory")

// ============ fp16 tensor-core GEMM1 + fused attention epilogue ============
// (unchanged from R14; MODE 1 only now)
template<int BN, int MODE>
__global__ void __launch_bounds__(256, 3) mma_gemm_kernel(
        const float* __restrict__ A, const __half* __restrict__ Bt,
        float* __restrict__ C, const float* __restrict__ av,
        const float* __restrict__ rv, int M, int N) {
    constexpr int LDS = 40;
    constexpr int WN  = BN / 4;
    constexpr int NJ  = WN / 16;
    extern __shared__ __half dyn[];
    __half* pA = dyn;                         // [2][64][LDS]
    __half* pB = dyn + 2 * 64 * LDS;          // [2][BN][LDS]

    int tid = threadIdx.x, lane = tid & 31, wid = tid >> 5;
    int wm = wid & 1, wn = wid >> 1;
    int row0 = blockIdx.y * 64, col0 = blockIdx.x * BN;
    float acc[2][2 * NJ][4] = {};

    int rA = tid >> 2, cA = (tid & 3) * 8;
    const float* aBase = &A[(size_t)(row0 + rA) * 256 + cA];
    bool aValid = (row0 + rA < M);

    auto loadB = [&](int k0, int b) {
        #pragma unroll
        for (int t = 0; t < BN / 64; t++) {
            int v = tid + t * 256;
            int r = v >> 2, c = (v & 3) * 8;
            cp16(smem_u32(pB + (b * BN + r) * LDS + c), &Bt[(size_t)(col0 + r) * 256 + k0 + c]);
        }
        CP_COMMIT();
    };
    auto storeA = [&](const float* fv, int b) {
        union { __half hh[8]; uint4 u; } uc;
        #pragma unroll
        for (int e = 0; e < 8; e++) uc.hh[e] = __float2half_rn(fv[e]);
        *(uint4*)(pA + (b * 64 + rA) * LDS + cA) = uc.u;
    };

    loadB(0, 0);
    {
        float fv[8] = {};
        if (aValid) { *(float4*)fv = *(const float4*)aBase; *(float4*)(fv + 4) = *(const float4*)(aBase + 4); }
        storeA(fv, 0);
    }
    CP_WAIT0();
    __syncthreads();

    for (int chunk = 0; chunk < 8; chunk++) {
        int cur = chunk & 1, nxt = chunk + 1;
        float fv[8] = {};
        if (nxt < 8) {
            loadB(nxt * 32, nxt & 1);
            if (aValid) {
                const float* ap = aBase + nxt * 32;
                *(float4*)fv = *(const float4*)ap;
                *(float4*)(fv + 4) = *(const float4*)(ap + 4);
            }
        }
        #pragma unroll
        for (int kk = 0; kk < 2; kk++) {
            int kc = kk * 16 + (lane >> 4) * 8;
            uint32_t af[2][4];
            #pragma unroll
            for (int mi = 0; mi < 2; mi++) {
                int r = wm * 32 + mi * 16 + (lane & 15);
                ldsm_x4(af[mi], pA + (cur * 64 + r) * LDS + kc);
            }
            #pragma unroll
            for (int nj = 0; nj < NJ; nj++) {
                uint32_t bf[4];
                int r = wn * WN + nj * 16 + (lane & 15);
                ldsm_x4(bf, pB + (cur * BN + r) * LDS + kc);
                #pragma unroll
                for (int half_ = 0; half_ < 2; half_++)
                    #pragma unroll
                    for (int mi = 0; mi < 2; mi++)
                        mma_f16(acc[mi][nj * 2 + half_], af[mi], bf[half_], bf[2 + half_]);
            }
        }
        if (nxt < 8) storeA(fv, nxt & 1);
        CP_WAIT0();
        __syncthreads();
    }

    // ---- epilogue: store fp16 feat + fused attention partials ----
    float elp[4] = {}, erp[4] = {};
    #pragma unroll
    for (int mi = 0; mi < 2; mi++) {
        #pragma unroll
        for (int f = 0; f < 2 * NJ; f++) {
            int r0 = row0 + wm * 32 + mi * 16 + (lane >> 2);
            int c  = col0 + wn * WN + f * 8 + (lane & 3) * 2;
            #pragma unroll
            for (int hh = 0; hh < 2; hh++) {
                int r = r0 + hh * 8;
                if (r >= M) continue;
                float v0 = acc[mi][f][hh * 2], v1 = acc[mi][f][hh * 2 + 1];
                int ri = mi * 2 + hh;
                *(__half2*)&g_feat1h[(size_t)r * 256 + c] = __floats2half2_rn(v0, v1);
                elp[ri] += v0 * av[c] + v1 * av[c + 1];
                erp[ri] += v0 * rv[c] + v1 * rv[c + 1];
            }
        }
    }
    #pragma unroll
    for (int ri = 0; ri < 4; ri++) {
        #pragma unroll
        for (int o = 1; o <= 2; o <<= 1) {
            elp[ri] += __shfl_xor_sync(0xffffffffu, elp[ri], o);
            erp[ri] += __shfl_xor_sync(0xffffffffu, erp[ri], o);
        }
    }
    if ((lane & 3) == 0) {
        int q = row0 + wm * 32 + (lane >> 2);
        int head = (col0 >> 5) + wn;
        #pragma unroll
        for (int ri = 0; ri < 4; ri++) {
            int r = q + (ri & 1) * 8 + (ri >> 1) * 16;
            if (r < M) {
                g_el1[r * H1 + head] = elp[ri];
                g_er1[r * H1 + head] = erp[ri];
            }
        }
    }
}

// ---------------- weight conversion (GEMM branch) ----------------
__global__ void convert_w_kernel(const float* __restrict__ W1, const float* __restrict__ W2,
                                 const float* __restrict__ resW2) {
    int i = blockIdx.x * blockDim.x + threadIdx.x;   // i = n*256 + k
    if (i < 256 * 256) {
        int n = i >> 8, k = i & 255;
        g_w1t[i] = __float2half_rn(W1[k * 256 + n]);
        if (n < 64) {
            float v = (n < 32) ? W2[k * 32 + n] : resW2[k * 32 + (n - 32)];
            g_wct[i] = __float2half_rn(v);
        }
    }
}

// ---------------- CSR branch ----------------
__global__ void hist_kernel(const int* __restrict__ dst) {
    int e = blockIdx.x * blockDim.x + threadIdx.x;
    if (e < EE) atomicAdd(&g_deg[dst[e]], 1);
    if (e < SCAN_BC) g_flag[e] = 0;
}
// Single-kernel exclusive scan with ordered inter-block spin sync (as R14).
__global__ void scan_fused_kernel() {
    __shared__ int sm[1024];
    __shared__ int base_s;
    int b = blockIdx.x, tid = threadIdx.x;
    int i = b * 1024 + tid;
    int v = (i < NN) ? g_deg[i] : 0;
    if (i < NN) g_deg[i] = 0;                 // self-reset for next replay
    sm[tid] = v;
    __syncthreads();
    #pragma unroll
    for (int off = 1; off < 1024; off <<= 1) {
        int t2 = (tid >= off) ? sm[tid - off] : 0;
        __syncthreads();
        sm[tid] += t2;
        __syncthreads();
    }
    int incl = sm[tid];
    if (tid == 1023) {
        g_bsum[b] = incl;
        __threadfence();
        atomicExch(&g_flag[b], 1);
    }
    if (tid == 0) {
        int acc = 0;
        for (int j = 0; j < b; j++) {
            while (atomicAdd(&g_flag[j], 0) == 0) {}
            acc += g_bsum[j];
        }
        base_s = acc;
    }
    __syncthreads();
    int r = base_s + incl - v;
    if (i < NN) { g_rowoff[i] = r; g_cursor[i] = r; }
    if (b == SCAN_BC - 1 && tid == 1023) g_rowoff[NN] = base_s + incl;
}
__global__ void scatter_kernel(const int* __restrict__ src, const int* __restrict__ dst) {
    int e = blockIdx.x * blockDim.x + threadIdx.x;
    if (e < EE) {
        int d = dst[e];
        int slot = atomicAdd(&g_cursor[d], 1);
        g_csr_src[slot] = src[e];
    }
}

// ============ FUSED layer1-aggregate + layer2-GEMM (+ attn epilogue) ============
// CTA = 64 nodes, 256 threads.
// Phase A: 8 warps x 8 nodes warp-per-node aggregation (R14 agg1 logic),
//          y written straight to smem as fp16; el2/er2 zeroed per node.
//          B tile (wct 64x256 fp16) streams in via cp.async underneath.
// Phase B: GEMM f2 = y @ wct from smem (A needs no staging), warps 2(M)x4(N),
//          fused el2/er2 attention epilogue (atomics target own rows only).
#define FLDS 264   // padded half stride: 528B rows, 33x16B (odd) -> LDSM conflict-free
__global__ void __launch_bounds__(256, 3) agg1_gemm2_kernel(
        const float* __restrict__ x, const float* __restrict__ b1,
        const float* __restrict__ av, const float* __restrict__ rv) {
    extern __shared__ __half fsm[];
    __half* sy = fsm;                 // [64][FLDS]
    __half* sB = fsm + 64 * FLDS;     // [64][FLDS]
    int tid = threadIdx.x, lane = tid & 31, wid = tid >> 5;
    int row0 = blockIdx.x * 64;

    // ---- B tile load (fully hidden under phase A) ----
    #pragma unroll
    for (int s2 = 0; s2 < 8; s2++) {
        int v = tid + s2 * 256;       // 2048 x 16B chunks
        int r = v >> 5, c8 = (v & 31) * 8;
        cp16(smem_u32(sB + r * FLDS + c8), &g_wct[r * 256 + c8]);
    }
    CP_COMMIT();

    // ---- phase A: aggregation for this CTA's 64 nodes ----
    int srcLane = lane >> 4;
    for (int q = 0; q < 8; q++) {
        int n = row0 + wid * 8 + q;
        if (n >= NN) break;
        if (lane == 0) { g_el2[n] = 0.f; g_er2[n] = 0.f; }
        int beg = g_rowoff[n], end = g_rowoff[n + 1];
        float er8 = (lane < H1) ? g_er1[n * H1 + lane] : 0.f;
        float2 acc[4] = {};
        float sv[4] = {};
        for (int i = beg; i < end; i++) {
            int sn = g_csr_src[i];
            float w8 = 0.f;
            if (lane < H1) {
                float e = g_el1[sn * H1 + lane] + er8;
                e = e > 0.f ? e : NEG_SLOPE * e;
                w8 = __expf(e);
            }
            const __half2* frow = (const __half2*)&g_feat1h[(size_t)sn * 256];
            #pragma unroll
            for (int p = 0; p < 4; p++) {
                float w = __shfl_sync(0xffffffffu, w8, 2 * p + srcLane);
                float2 f = __half22float2(frow[p * 32 + lane]);
                acc[p].x += w * f.x;
                acc[p].y += w * f.y;
                sv[p] += w;
            }
        }
        int loc = wid * 8 + q;
        #pragma unroll
        for (int p = 0; p < 4; p++) {
            float inv = (end > beg) ? 1.0f / sv[p] : 0.f;
            int o = n * 256 + p * 64 + lane * 2;
            float2 xr = *(const float2*)&x[o];
            float2 bb = *(const float2*)&b1[p * 64 + lane * 2];
            float r0 = fmaxf(acc[p].x * inv + xr.x + bb.x, 0.f);
            float r1 = fmaxf(acc[p].y * inv + xr.y + bb.y, 0.f);
            *(__half2*)&sy[loc * FLDS + p * 64 + lane * 2] = __floats2half2_rn(r0, r1);
        }
    }
    CP_WAIT0();
    __syncthreads();

    // ---- phase B: GEMM from smem (BM=64, BN=64, warps 2(M)x4(N), WN=16) ----
    int wm = wid & 1, wn = wid >> 1;
    float acc[2][2][4] = {};
    #pragma unroll
    for (int kk = 0; kk < 16; kk++) {
        int kc = kk * 16 + (lane >> 4) * 8;
        uint32_t af[2][4];
        #pragma unroll
        for (int mi = 0; mi < 2; mi++) {
            int r = wm * 32 + mi * 16 + (lane & 15);
            ldsm_x4(af[mi], sy + r * FLDS + kc);
        }
        uint32_t bf[4];
        int rb = wn * 16 + (lane & 15);
        ldsm_x4(bf, sB + rb * FLDS + kc);
        #pragma unroll
        for (int half_ = 0; half_ < 2; half_++)
            #pragma unroll
            for (int mi = 0; mi < 2; mi++)
                mma_f16(acc[mi][half_], af[mi], bf[half_], bf[2 + half_]);
    }

    // ---- epilogue: f2 / f2h stores + el2/er2 attention partials ----
    float elp[4] = {}, erp[4] = {};
    #pragma unroll
    for (int mi = 0; mi < 2; mi++) {
        #pragma unroll
        for (int f = 0; f < 2; f++) {
            int r0 = row0 + wm * 32 + mi * 16 + (lane >> 2);
            int c  = wn * 16 + f * 8 + (lane & 3) * 2;
            #pragma unroll
            for (int hh = 0; hh < 2; hh++) {
                int r = r0 + hh * 8;
                if (r >= NN) continue;
                float v0 = acc[mi][f][hh * 2], v1 = acc[mi][f][hh * 2 + 1];
                int ri = mi * 2 + hh;
                *(float2*)&g_f2[(size_t)r * 64 + c] = make_float2(v0, v1);
                if (c < 32) {
                    *(__half2*)&g_f2h[(size_t)r * 32 + c] = __floats2half2_rn(v0, v1);
                    elp[ri] += v0 * av[c] + v1 * av[c + 1];
                    erp[ri] += v0 * rv[c] + v1 * rv[c + 1];
                }
            }
        }
    }
    #pragma unroll
    for (int ri = 0; ri < 4; ri++) {
        #pragma unroll
        for (int o = 1; o <= 2; o <<= 1) {
            elp[ri] += __shfl_xor_sync(0xffffffffu, elp[ri], o);
            erp[ri] += __shfl_xor_sync(0xffffffffu, erp[ri], o);
        }
    }
    if ((lane & 3) == 0 && wn < 2) {
        int q = row0 + wm * 32 + (lane >> 2);
        #pragma unroll
        for (int ri = 0; ri < 4; ri++) {
            int r = q + (ri & 1) * 8 + (ri >> 1) * 16;
            if (r < NN) {
                atomicAdd(&g_el2[r], elp[ri]);
                atomicAdd(&g_er2[r], erp[ri]);
            }
        }
    }
}

// ---------------- layer2 fused softmax+aggregate (half-warp parity, half2) ----
__global__ void agg2_kernel(const float* __restrict__ b2, float* __restrict__ out) {
    int t = blockIdx.x * blockDim.x + threadIdx.x;
    int n = t >> 5;
    if (n >= NN) return;
    int lane = t & 31;
    int par = lane >> 4;
    int cl = (lane & 15) * 2;
    int beg = g_rowoff[n], end = g_rowoff[n + 1];
    float ern = g_er2[n];
    float2 acc = make_float2(0.f, 0.f);
    float s = 0.f;
    for (int i = beg + par; i < end; i += 2) {
        int sn = g_csr_src[i];
        float e0 = g_el2[sn] + ern;
        e0 = e0 > 0.f ? e0 : NEG_SLOPE * e0;
        float w0 = __expf(e0);
        __half2 hv = *(const __half2*)&g_f2h[(size_t)sn * 32 + cl];
        float2 f = __half22float2(hv);
        s += w0;
        acc.x += w0 * f.x;
        acc.y += w0 * f.y;
    }
    acc.x += __shfl_xor_sync(0xffffffffu, acc.x, 16);
    acc.y += __shfl_xor_sync(0xffffffffu, acc.y, 16);
    s     += __shfl_xor_sync(0xffffffffu, s, 16);
    if (par == 0) {
        float inv = (end > beg) ? 1.0f / s : 0.f;
        float2 rr = *(const float2*)&g_f2[(size_t)n * 64 + 32 + cl];
        float2 bb = *(const float2*)&b2[cl];
        *(float2*)&out[n * 32 + cl] =
            make_float2(acc.x * inv + rr.x + bb.x, acc.y * inv + rr.y + bb.y);
    }
}

// ---------------- side stream + events (static init; not device allocations) ----
static cudaStream_t g_s2;
static cudaEvent_t  g_evFork, g_evJoin;
static struct StreamInit {
    StreamInit() {
        cudaStreamCreateWithFlags(&g_s2, cudaStreamNonBlocking);
        cudaEventCreateWithFlags(&g_evFork, cudaEventDisableTiming);
        cudaEventCreateWithFlags(&g_evJoin, cudaEventDisableTiming);
    }
} g_streamInit;

// ---------------- launch ----------------
extern "C" void kernel_launch(void* const* d_in, const int* in_sizes, int n_in,
                              void* d_out, int out_size) {
    const float* x     = (const float*)d_in[0];
    const int*   src   = (const int*)d_in[1];
    const int*   dst   = (const int*)d_in[2];
    const float* W1    = (const float*)d_in[3];
    const float* al1   = (const float*)d_in[4];
    const float* ar1   = (const float*)d_in[5];
    const float* b1    = (const float*)d_in[6];
    const float* W2    = (const float*)d_in[7];
    const float* al2   = (const float*)d_in[8];
    const float* ar2   = (const float*)d_in[9];
    const float* resW2 = (const float*)d_in[10];
    const float* b2    = (const float*)d_in[11];
    float* out = (float*)d_out;

    __half *w1t;
    cudaGetSymbolAddress((void**)&w1t, g_w1t);

    const int LDSC = 40;
    const int smem128 = (2 * 64 * LDSC + 2 * 128 * LDSC) * 2;   // 30720 B
    const int smemF   = 2 * 64 * FLDS * 2;                      // 67584 B
    cudaFuncSetAttribute(mma_gemm_kernel<128, 1>,
                         cudaFuncAttributeMaxDynamicSharedMemorySize, smem128);
    cudaFuncSetAttribute(agg1_gemm2_kernel,
                         cudaFuncAttributeMaxDynamicSharedMemorySize, smemF);

    // ---- fork: CSR branch on side stream ----
    cudaEventRecord(g_evFork, 0);
    cudaStreamWaitEvent(g_s2, g_evFork, 0);

    hist_kernel<<<(EE + 255) / 256, 256, 0, g_s2>>>(dst);
    scan_fused_kernel<<<SCAN_BC, 1024, 0, g_s2>>>();
    scatter_kernel<<<(EE + 255) / 256, 256, 0, g_s2>>>(src, dst);
    cudaEventRecord(g_evJoin, g_s2);

    // ---- main branch: weights + layer-1 GEMM (fused attn) ----
    convert_w_kernel<<<(256 * 256 + 255) / 256, 256>>>(W1, W2, resW2);
    mma_gemm_kernel<128, 1><<<dim3(2, (NN + 63) / 64), 256, smem128>>>(
        x, w1t, nullptr, al1, ar1, NN, 256);

    // ---- join, then the fused tail ----
    cudaStreamWaitEvent(0, g_evJoin, 0);
    agg1_gemm2_kernel<<<(NN + 63) / 64, 256, smemF>>>(x, b1, al2, ar2);
    agg2_kernel<<<(NN * 32 + 255) / 256, 256>>>(b2, out);
}

// round 16
// speedup vs baseline: 1.4679x; 1.4679x over previous
#include <cuda_runtime.h>
#include <cuda_fp16.h>
#include <math.h>
#include <stdint.h>

#define NN 50000
#define EE 800000
#define H1 8
#define NEG_SLOPE 0.2f
#define SCAN_BC ((NN + 1023) / 1024)   // 49

// ---------------- scratch (device globals; no allocation allowed) ----------------
__device__ __half g_feat1h[NN * 256];        // layer1 features (fp16 gather)
__device__ float  g_y[NN * 256];             // layer1 output (fp32, after relu)
__device__ float  g_el1[NN * H1];
__device__ float  g_er1[NN * H1];
__device__ float  g_f2[NN * 64];             // [ feat2 (0..31) | res2 (32..63) ] fp32
__device__ __half g_f2h[NN * 32];            // fp16 copy of feat2 (agg2 gather)
__device__ float  g_el2[NN];
__device__ float  g_er2[NN];
__device__ __half g_w1t[256 * 256];          // W1^T [n][k] fp16
__device__ __half g_wct[64 * 256];           // [W2|resW2]^T [n][k] fp16
__device__ int   g_deg[NN];                  // zero-init at load; self-reset each run
__device__ int   g_rowoff[NN + 1];
__device__ int   g_cursor[NN];
__device__ int   g_csr_src[EE];
__device__ int   g_bsum[SCAN_BC];
__device__ int   g_flag[SCAN_BC];

// ---------------- helpers ----------------
__device__ __forceinline__ uint32_t smem_u32(const void* p) {
    uint32_t a;
    asm("{ .reg .u64 t; cvta.to.shared.u64 t, %1; cvt.u32.u64 %0, t; }" : "=r"(a) : "l"(p));
    return a;
}
__device__ __forceinline__ void ldsm_x4(uint32_t (&r)[4], const void* p) {
    uint32_t a = smem_u32(p);
    asm volatile("ldmatrix.sync.aligned.m8n8.x4.shared.b16 {%0,%1,%2,%3}, [%4];"
                 : "=r"(r[0]), "=r"(r[1]), "=r"(r[2]), "=r"(r[3]) : "r"(a));
}
__device__ __forceinline__ void mma_f16(float (&d)[4], const uint32_t (&a)[4],
                                        uint32_t b0, uint32_t b1) {
    asm volatile("mma.sync.aligned.m16n8k16.row.col.f32.f16.f16.f32 "
                 "{%0,%1,%2,%3},{%4,%5,%6,%7},{%8,%9},{%0,%1,%2,%3};"
                 : "+f"(d[0]), "+f"(d[1]), "+f"(d[2]), "+f"(d[3])
                 : "r"(a[0]), "r"(a[1]), "r"(a[2]), "r"(a[3]), "r"(b0), "r"(b1));
}
__device__ __forceinline__ void cp16(uint32_t dst, const void* src) {
    asm volatile("cp.async.cg.shared.global [%0], [%1], 16;" :: "r"(dst), "l"(src));
}
#define CP_COMMIT() asm volatile("cp.async.commit_group;" ::: "memory")
#define CP_WAIT0()  asm volatile("cp.async.wait_group 0;" ::: "memory")

// ============ fp16 tensor-core GEMM1 + fused attention epilogue (as R14) ============
template<int BN, int MODE>
__global__ void __launch_bounds__(256, 3) mma_gemm_kernel(
        const float* __restrict__ A, const __half* __restrict__ Bt,
        float* __restrict__ C, const float* __restrict__ av,
        const float* __restrict__ rv, int M, int N) {
    constexpr int LDS = 40;
    constexpr int WN  = BN / 4;
    constexpr int NJ  = WN / 16;
    extern __shared__ __half dyn[];
    __half* pA = dyn;                         // [2][64][LDS]
    __half* pB = dyn + 2 * 64 * LDS;          // [2][BN][LDS]

    int tid = threadIdx.x, lane = tid & 31, wid = tid >> 5;
    int wm = wid & 1, wn = wid >> 1;
    int row0 = blockIdx.y * 64, col0 = blockIdx.x * BN;
    float acc[2][2 * NJ][4] = {};

    int rA = tid >> 2, cA = (tid & 3) * 8;
    const float* aBase = &A[(size_t)(row0 + rA) * 256 + cA];
    bool aValid = (row0 + rA < M);

    auto loadB = [&](int k0, int b) {
        #pragma unroll
        for (int t = 0; t < BN / 64; t++) {
            int v = tid + t * 256;
            int r = v >> 2, c = (v & 3) * 8;
            cp16(smem_u32(pB + (b * BN + r) * LDS + c), &Bt[(size_t)(col0 + r) * 256 + k0 + c]);
        }
        CP_COMMIT();
    };
    auto storeA = [&](const float* fv, int b) {
        union { __half hh[8]; uint4 u; } uc;
        #pragma unroll
        for (int e = 0; e < 8; e++) uc.hh[e] = __float2half_rn(fv[e]);
        *(uint4*)(pA + (b * 64 + rA) * LDS + cA) = uc.u;
    };

    loadB(0, 0);
    {
        float fv[8] = {};
        if (aValid) { *(float4*)fv = *(const float4*)aBase; *(float4*)(fv + 4) = *(const float4*)(aBase + 4); }
        storeA(fv, 0);
    }
    CP_WAIT0();
    __syncthreads();

    for (int chunk = 0; chunk < 8; chunk++) {
        int cur = chunk & 1, nxt = chunk + 1;
        float fv[8] = {};
        if (nxt < 8) {
            loadB(nxt * 32, nxt & 1);
            if (aValid) {
                const float* ap = aBase + nxt * 32;
                *(float4*)fv = *(const float4*)ap;
                *(float4*)(fv + 4) = *(const float4*)(ap + 4);
            }
        }
        #pragma unroll
        for (int kk = 0; kk < 2; kk++) {
            int kc = kk * 16 + (lane >> 4) * 8;
            uint32_t af[2][4];
            #pragma unroll
            for (int mi = 0; mi < 2; mi++) {
                int r = wm * 32 + mi * 16 + (lane & 15);
                ldsm_x4(af[mi], pA + (cur * 64 + r) * LDS + kc);
            }
            #pragma unroll
            for (int nj = 0; nj < NJ; nj++) {
                uint32_t bf[4];
                int r = wn * WN + nj * 16 + (lane & 15);
                ldsm_x4(bf, pB + (cur * BN + r) * LDS + kc);
                #pragma unroll
                for (int half_ = 0; half_ < 2; half_++)
                    #pragma unroll
                    for (int mi = 0; mi < 2; mi++)
                        mma_f16(acc[mi][nj * 2 + half_], af[mi], bf[half_], bf[2 + half_]);
            }
        }
        if (nxt < 8) storeA(fv, nxt & 1);
        CP_WAIT0();
        __syncthreads();
    }

    // ---- epilogue: store fp16 feat + fused attention partials ----
    float elp[4] = {}, erp[4] = {};
    #pragma unroll
    for (int mi = 0; mi < 2; mi++) {
        #pragma unroll
        for (int f = 0; f < 2 * NJ; f++) {
            int r0 = row0 + wm * 32 + mi * 16 + (lane >> 2);
            int c  = col0 + wn * WN + f * 8 + (lane & 3) * 2;
            #pragma unroll
            for (int hh = 0; hh < 2; hh++) {
                int r = r0 + hh * 8;
                if (r >= M) continue;
                float v0 = acc[mi][f][hh * 2], v1 = acc[mi][f][hh * 2 + 1];
                int ri = mi * 2 + hh;
                *(__half2*)&g_feat1h[(size_t)r * 256 + c] = __floats2half2_rn(v0, v1);
                elp[ri] += v0 * av[c] + v1 * av[c + 1];
                erp[ri] += v0 * rv[c] + v1 * rv[c + 1];
            }
        }
    }
    #pragma unroll
    for (int ri = 0; ri < 4; ri++) {
        #pragma unroll
        for (int o = 1; o <= 2; o <<= 1) {
            elp[ri] += __shfl_xor_sync(0xffffffffu, elp[ri], o);
            erp[ri] += __shfl_xor_sync(0xffffffffu, erp[ri], o);
        }
    }
    if ((lane & 3) == 0) {
        int q = row0 + wm * 32 + (lane >> 2);
        int head = (col0 >> 5) + wn;
        #pragma unroll
        for (int ri = 0; ri < 4; ri++) {
            int r = q + (ri & 1) * 8 + (ri >> 1) * 16;
            if (r < M) {
                g_el1[r * H1 + head] = elp[ri];
                g_er1[r * H1 + head] = erp[ri];
            }
        }
    }
}

// ============ fp16 GEMM2 (MODE 2: f2 + f2h + el2/er2 atomics), as R14 ============
template<int BN>
__global__ void __launch_bounds__(256, 3) mma_gemm2_kernel(
        const float* __restrict__ A, const __half* __restrict__ Bt,
        float* __restrict__ C, const float* __restrict__ av,
        const float* __restrict__ rv, int M, int N) {
    constexpr int LDS = 40;
    constexpr int WN  = BN / 4;
    constexpr int NJ  = WN / 16;
    extern __shared__ __half dyn[];
    __half* pA = dyn;
    __half* pB = dyn + 2 * 64 * LDS;

    int tid = threadIdx.x, lane = tid & 31, wid = tid >> 5;
    int wm = wid & 1, wn = wid >> 1;
    int row0 = blockIdx.y * 64, col0 = blockIdx.x * BN;
    float acc[2][2 * NJ][4] = {};

    int rA = tid >> 2, cA = (tid & 3) * 8;
    const float* aBase = &A[(size_t)(row0 + rA) * 256 + cA];
    bool aValid = (row0 + rA < M);

    auto loadB = [&](int k0, int b) {
        #pragma unroll
        for (int t = 0; t < BN / 64; t++) {
            int v = tid + t * 256;
            int r = v >> 2, c = (v & 3) * 8;
            cp16(smem_u32(pB + (b * BN + r) * LDS + c), &Bt[(size_t)(col0 + r) * 256 + k0 + c]);
        }
        CP_COMMIT();
    };
    auto storeA = [&](const float* fv, int b) {
        union { __half hh[8]; uint4 u; } uc;
        #pragma unroll
        for (int e = 0; e < 8; e++) uc.hh[e] = __float2half_rn(fv[e]);
        *(uint4*)(pA + (b * 64 + rA) * LDS + cA) = uc.u;
    };

    loadB(0, 0);
    {
        float fv[8] = {};
        if (aValid) { *(float4*)fv = *(const float4*)aBase; *(float4*)(fv + 4) = *(const float4*)(aBase + 4); }
        storeA(fv, 0);
    }
    CP_WAIT0();
    __syncthreads();

    for (int chunk = 0; chunk < 8; chunk++) {
        int cur = chunk & 1, nxt = chunk + 1;
        float fv[8] = {};
        if (nxt < 8) {
            loadB(nxt * 32, nxt & 1);
            if (aValid) {
                const float* ap = aBase + nxt * 32;
                *(float4*)fv = *(const float4*)ap;
                *(float4*)(fv + 4) = *(const float4*)(ap + 4);
            }
        }
        #pragma unroll
        for (int kk = 0; kk < 2; kk++) {
            int kc = kk * 16 + (lane >> 4) * 8;
            uint32_t af[2][4];
            #pragma unroll
            for (int mi = 0; mi < 2; mi++) {
                int r = wm * 32 + mi * 16 + (lane & 15);
                ldsm_x4(af[mi], pA + (cur * 64 + r) * LDS + kc);
            }
            #pragma unroll
            for (int nj = 0; nj < NJ; nj++) {
                uint32_t bf[4];
                int r = wn * WN + nj * 16 + (lane & 15);
                ldsm_x4(bf, pB + (cur * BN + r) * LDS + kc);
                #pragma unroll
                for (int half_ = 0; half_ < 2; half_++)
                    #pragma unroll
                    for (int mi = 0; mi < 2; mi++)
                        mma_f16(acc[mi][nj * 2 + half_], af[mi], bf[half_], bf[2 + half_]);
            }
        }
        if (nxt < 8) storeA(fv, nxt & 1);
        CP_WAIT0();
        __syncthreads();
    }

    float elp[4] = {}, erp[4] = {};
    #pragma unroll
    for (int mi = 0; mi < 2; mi++) {
        #pragma unroll
        for (int f = 0; f < 2 * NJ; f++) {
            int r0 = row0 + wm * 32 + mi * 16 + (lane >> 2);
            int c  = col0 + wn * WN + f * 8 + (lane & 3) * 2;
            #pragma unroll
            for (int hh = 0; hh < 2; hh++) {
                int r = r0 + hh * 8;
                if (r >= M) continue;
                float v0 = acc[mi][f][hh * 2], v1 = acc[mi][f][hh * 2 + 1];
                int ri = mi * 2 + hh;
                *(float2*)&C[(size_t)r * N + c] = make_float2(v0, v1);
                if (c < 32) {
                    *(__half2*)&g_f2h[(size_t)r * 32 + c] = __floats2half2_rn(v0, v1);
                    elp[ri] += v0 * av[c] + v1 * av[c + 1];
                    erp[ri] += v0 * rv[c] + v1 * rv[c + 1];
                }
            }
        }
    }
    #pragma unroll
    for (int ri = 0; ri < 4; ri++) {
        #pragma unroll
        for (int o = 1; o <= 2; o <<= 1) {
            elp[ri] += __shfl_xor_sync(0xffffffffu, elp[ri], o);
            erp[ri] += __shfl_xor_sync(0xffffffffu, erp[ri], o);
        }
    }
    if ((lane & 3) == 0 && wn < 2) {
        int q = row0 + wm * 32 + (lane >> 2);
        #pragma unroll
        for (int ri = 0; ri < 4; ri++) {
            int r = q + (ri & 1) * 8 + (ri >> 1) * 16;
            if (r < M) {
                atomicAdd(&g_el2[r], elp[ri]);
                atomicAdd(&g_er2[r], erp[ri]);
            }
        }
    }
}

// ---------------- weight conversion (GEMM branch) ----------------
__global__ void convert_w_kernel(const float* __restrict__ W1, const float* __restrict__ W2,
                                 const float* __restrict__ resW2) {
    int i = blockIdx.x * blockDim.x + threadIdx.x;   // i = n*256 + k
    if (i < 256 * 256) {
        int n = i >> 8, k = i & 255;
        g_w1t[i] = __float2half_rn(W1[k * 256 + n]);
        if (n < 64) {
            float v = (n < 32) ? W2[k * 32 + n] : resW2[k * 32 + (n - 32)];
            g_wct[i] = __float2half_rn(v);
        }
    }
}

// ---------------- CSR branch ----------------
__global__ void hist_kernel(const int* __restrict__ dst) {
    int e = blockIdx.x * blockDim.x + threadIdx.x;
    if (e < EE) atomicAdd(&g_deg[dst[e]], 1);
    if (e < SCAN_BC) g_flag[e] = 0;
}
__global__ void scan_fused_kernel() {
    __shared__ int sm[1024];
    __shared__ int base_s;
    int b = blockIdx.x, tid = threadIdx.x;
    int i = b * 1024 + tid;
    int v = (i < NN) ? g_deg[i] : 0;
    if (i < NN) g_deg[i] = 0;                 // self-reset for next replay
    sm[tid] = v;
    __syncthreads();
    #pragma unroll
    for (int off = 1; off < 1024; off <<= 1) {
        int t2 = (tid >= off) ? sm[tid - off] : 0;
        __syncthreads();
        sm[tid] += t2;
        __syncthreads();
    }
    int incl = sm[tid];
    if (tid == 1023) {
        g_bsum[b] = incl;
        __threadfence();
        atomicExch(&g_flag[b], 1);
    }
    if (tid == 0) {
        int acc = 0;
        for (int j = 0; j < b; j++) {
            while (atomicAdd(&g_flag[j], 0) == 0) {}
            acc += g_bsum[j];
        }
        base_s = acc;
    }
    __syncthreads();
    int r = base_s + incl - v;
    if (i < NN) { g_rowoff[i] = r; g_cursor[i] = r; }
    if (b == SCAN_BC - 1 && tid == 1023) g_rowoff[NN] = base_s + incl;
}
__global__ void scatter_kernel(const int* __restrict__ src, const int* __restrict__ dst) {
    int e = blockIdx.x * blockDim.x + threadIdx.x;
    if (e < EE) {
        int d = dst[e];
        int slot = atomicAdd(&g_cursor[d], 1);
        g_csr_src[slot] = src[e];
    }
}

// ---------------- layer1 softmax+aggregate: WARP per node, LDG.128 gather ------
// Lane loads uint4 (8 halfs = 8 cols) at lane*8; all 8 cols in one head
// (head = lane>>2). 1 wide load per edge instead of 4 narrow ones; 2x unroll.
__global__ void __launch_bounds__(256) agg1_kernel(const float* __restrict__ x,
                                                   const float* __restrict__ b1) {
    int t = blockIdx.x * blockDim.x + threadIdx.x;
    int n = t >> 5;
    if (n >= NN) return;
    int lane = t & 31;
    if (lane == 0) { g_el2[n] = 0.f; g_er2[n] = 0.f; }
    int beg = g_rowoff[n], end = g_rowoff[n + 1];
    float er8 = (lane < H1) ? g_er1[n * H1 + lane] : 0.f;
    int myhead = lane >> 2;
    float2 acc[4] = {};
    float sv = 0.f;
    int i = beg;
    for (; i + 1 < end; i += 2) {
        int sn0 = g_csr_src[i], sn1 = g_csr_src[i + 1];
        float w80 = 0.f, w81 = 0.f;
        if (lane < H1) {
            float e0 = g_el1[sn0 * H1 + lane] + er8;
            float e1 = g_el1[sn1 * H1 + lane] + er8;
            e0 = e0 > 0.f ? e0 : NEG_SLOPE * e0;
            e1 = e1 > 0.f ? e1 : NEG_SLOPE * e1;
            w80 = __expf(e0);
            w81 = __expf(e1);
        }
        float w0 = __shfl_sync(0xffffffffu, w80, myhead);
        float w1 = __shfl_sync(0xffffffffu, w81, myhead);
        uint4 u0 = *(const uint4*)&g_feat1h[(size_t)sn0 * 256 + lane * 8];
        uint4 u1 = *(const uint4*)&g_feat1h[(size_t)sn1 * 256 + lane * 8];
        const __half2* h0 = (const __half2*)&u0;
        const __half2* h1 = (const __half2*)&u1;
        #pragma unroll
        for (int p = 0; p < 4; p++) {
            float2 f0 = __half22float2(h0[p]);
            float2 f1 = __half22float2(h1[p]);
            acc[p].x += w0 * f0.x + w1 * f1.x;
            acc[p].y += w0 * f0.y + w1 * f1.y;
        }
        sv += w0 + w1;
    }
    if (i < end) {
        int sn0 = g_csr_src[i];
        float w80 = 0.f;
        if (lane < H1) {
            float e0 = g_el1[sn0 * H1 + lane] + er8;
            e0 = e0 > 0.f ? e0 : NEG_SLOPE * e0;
            w80 = __expf(e0);
        }
        float w0 = __shfl_sync(0xffffffffu, w80, myhead);
        uint4 u0 = *(const uint4*)&g_feat1h[(size_t)sn0 * 256 + lane * 8];
        const __half2* h0 = (const __half2*)&u0;
        #pragma unroll
        for (int p = 0; p < 4; p++) {
            float2 f0 = __half22float2(h0[p]);
            acc[p].x += w0 * f0.x;
            acc[p].y += w0 * f0.y;
        }
        sv += w0;
    }
    float inv = (end > beg) ? 1.0f / sv : 0.f;
    int o = n * 256 + lane * 8;
    float4 x0 = *(const float4*)&x[o];
    float4 x1 = *(const float4*)&x[o + 4];
    float4 bb0 = *(const float4*)&b1[lane * 8];
    float4 bb1 = *(const float4*)&b1[lane * 8 + 4];
    float4 r0, r1;
    r0.x = fmaxf(acc[0].x * inv + x0.x + bb0.x, 0.f);
    r0.y = fmaxf(acc[0].y * inv + x0.y + bb0.y, 0.f);
    r0.z = fmaxf(acc[1].x * inv + x0.z + bb0.z, 0.f);
    r0.w = fmaxf(acc[1].y * inv + x0.w + bb0.w, 0.f);
    r1.x = fmaxf(acc[2].x * inv + x1.x + bb1.x, 0.f);
    r1.y = fmaxf(acc[2].y * inv + x1.y + bb1.y, 0.f);
    r1.z = fmaxf(acc[3].x * inv + x1.z + bb1.z, 0.f);
    r1.w = fmaxf(acc[3].y * inv + x1.w + bb1.w, 0.f);
    *(float4*)&g_y[o] = r0;
    *(float4*)&g_y[o + 4] = r1;
}

// ---------------- layer2 fused softmax+aggregate (half-warp parity, half2) ----
__global__ void agg2_kernel(const float* __restrict__ b2, float* __restrict__ out) {
    int t = blockIdx.x * blockDim.x + threadIdx.x;
    int n = t >> 5;
    if (n >= NN) return;
    int lane = t & 31;
    int par = lane >> 4;
    int cl = (lane & 15) * 2;
    int beg = g_rowoff[n], end = g_rowoff[n + 1];
    float ern = g_er2[n];
    float2 acc = make_float2(0.f, 0.f);
    float s = 0.f;
    for (int i = beg + par; i < end; i += 2) {
        int sn = g_csr_src[i];
        float e0 = g_el2[sn] + ern;
        e0 = e0 > 0.f ? e0 : NEG_SLOPE * e0;
        float w0 = __expf(e0);
        __half2 hv = *(const __half2*)&g_f2h[(size_t)sn * 32 + cl];
        float2 f = __half22float2(hv);
        s += w0;
        acc.x += w0 * f.x;
        acc.y += w0 * f.y;
    }
    acc.x += __shfl_xor_sync(0xffffffffu, acc.x, 16);
    acc.y += __shfl_xor_sync(0xffffffffu, acc.y, 16);
    s     += __shfl_xor_sync(0xffffffffu, s, 16);
    if (par == 0) {
        float inv = (end > beg) ? 1.0f / s : 0.f;
        float2 rr = *(const float2*)&g_f2[(size_t)n * 64 + 32 + cl];
        float2 bb = *(const float2*)&b2[cl];
        *(float2*)&out[n * 32 + cl] =
            make_float2(acc.x * inv + rr.x + bb.x, acc.y * inv + rr.y + bb.y);
    }
}

// ---------------- side stream + events (static init; not device allocations) ----
static cudaStream_t g_s2;
static cudaEvent_t  g_evFork, g_evJoin;
static struct StreamInit {
    StreamInit() {
        cudaStreamCreateWithFlags(&g_s2, cudaStreamNonBlocking);
        cudaEventCreateWithFlags(&g_evFork, cudaEventDisableTiming);
        cudaEventCreateWithFlags(&g_evJoin, cudaEventDisableTiming);
    }
} g_streamInit;

// ---------------- launch: parallel branches; scatter placed 4th for profiling ----
extern "C" void kernel_launch(void* const* d_in, const int* in_sizes, int n_in,
                              void* d_out, int out_size) {
    const float* x     = (const float*)d_in[0];
    const int*   src   = (const int*)d_in[1];
    const int*   dst   = (const int*)d_in[2];
    const float* W1    = (const float*)d_in[3];
    const float* al1   = (const float*)d_in[4];
    const float* ar1   = (const float*)d_in[5];
    const float* b1    = (const float*)d_in[6];
    const float* W2    = (const float*)d_in[7];
    const float* al2   = (const float*)d_in[8];
    const float* ar2   = (const float*)d_in[9];
    const float* resW2 = (const float*)d_in[10];
    const float* b2    = (const float*)d_in[11];
    float* out = (float*)d_out;

    float *yb, *f2;
    __half *w1t, *wct;
    cudaGetSymbolAddress((void**)&yb,   g_y);
    cudaGetSymbolAddress((void**)&f2,   g_f2);
    cudaGetSymbolAddress((void**)&w1t,  g_w1t);
    cudaGetSymbolAddress((void**)&wct,  g_wct);

    const int LDSC = 40;
    const int smem128 = (2 * 64 * LDSC + 2 * 128 * LDSC) * 2;   // 30720 B
    const int smem64  = (2 * 64 * LDSC + 2 * 64 * LDSC) * 2;    // 20480 B
    cudaFuncSetAttribute(mma_gemm_kernel<128, 1>,
                         cudaFuncAttributeMaxDynamicSharedMemorySize, smem128);
    cudaFuncSetAttribute(mma_gemm2_kernel<64>,
                         cudaFuncAttributeMaxDynamicSharedMemorySize, smem64);

    // ---- fork: CSR branch on side stream ----
    cudaEventRecord(g_evFork, 0);
    cudaStreamWaitEvent(g_s2, g_evFork, 0);

    hist_kernel<<<(EE + 255) / 256, 256, 0, g_s2>>>(dst);             // 1
    scan_fused_kernel<<<SCAN_BC, 1024, 0, g_s2>>>();                  // 2
    convert_w_kernel<<<(256 * 256 + 255) / 256, 256>>>(W1, W2, resW2);// 3 (main)
    scatter_kernel<<<(EE + 255) / 256, 256, 0, g_s2>>>(src, dst);     // 4 (profiled)
    cudaEventRecord(g_evJoin, g_s2);

    mma_gemm_kernel<128, 1><<<dim3(2, (NN + 63) / 64), 256, smem128>>>(
        x, w1t, nullptr, al1, ar1, NN, 256);                          // 5

    // ---- join, then the serial tail ----
    cudaStreamWaitEvent(0, g_evJoin, 0);
    agg1_kernel<<<(NN * 32 + 255) / 256, 256>>>(x, b1);               // 6
    mma_gemm2_kernel<64><<<dim3(1, (NN + 63) / 64), 256, smem64>>>(
        yb, wct, f2, al2, ar2, NN, 64);                               // 7
    agg2_kernel<<<(NN * 32 + 255) / 256, 256>>>(b2, out);             // 8
}